// round 1
// baseline (speedup 1.0000x reference)
#include <cuda_runtime.h>
#include <cuda_bf16.h>
#include <math.h>

// Problem constants
#define BATCH 2
#define SEQ   2048
#define DMODEL 1024
#define NHEAD 16
#define DK    64
#define MROWS (BATCH * SEQ)      // 4096

// Scratch (device globals; allocations are forbidden)
__device__ float g_qh[BATCH * NHEAD * SEQ * DK];   // [B,H,S,DK]
__device__ float g_kh[BATCH * NHEAD * SEQ * DK];
__device__ float g_vh[BATCH * NHEAD * SEQ * DK];
__device__ float g_ctx[BATCH * SEQ * DMODEL];      // [B,S,D]

// ----------------------------------------------------------------------------
// SGEMM (NT): C[m,n] = sum_k A[m,k] * W[n,k], M=4096, N=1024, K=1024
// dst 0/1/2 -> write to g_qh/g_kh/g_vh in [B,H,S,DK] layout
// dst 3     -> write flat to Cflat[m*1024 + n]
// Tile: 128x128x8, 256 threads, 8x8 per thread.
// ----------------------------------------------------------------------------
__global__ void __launch_bounds__(256)
sgemm_nt(const float* __restrict__ A, const float* __restrict__ W,
         float* __restrict__ Cflat, int dst) {
    __shared__ float sA[8][128];
    __shared__ float sB[8][128];

    const int tid = threadIdx.x;
    const int lr = tid >> 1;           // 0..127 : row within tile to load
    const int lc = (tid & 1) << 2;     // 0 or 4 : k-offset within 8-wide k slab
    const int m0 = blockIdx.y * 128;
    const int n0 = blockIdx.x * 128;
    const int tn = (tid & 15) << 3;    // 0..120 : col offset of 8x8 micro tile
    const int tm = (tid >> 4) << 3;    // 0..120 : row offset

    const float* Aptr = A + (size_t)(m0 + lr) * DMODEL + lc;
    const float* Wptr = W + (size_t)(n0 + lr) * DMODEL + lc;

    float acc[8][8];
    #pragma unroll
    for (int i = 0; i < 8; i++)
        #pragma unroll
        for (int j = 0; j < 8; j++) acc[i][j] = 0.f;

    for (int k0 = 0; k0 < DMODEL; k0 += 8) {
        float4 av = *reinterpret_cast<const float4*>(Aptr + k0);
        float4 wv = *reinterpret_cast<const float4*>(Wptr + k0);
        __syncthreads();
        sA[lc + 0][lr] = av.x; sA[lc + 1][lr] = av.y;
        sA[lc + 2][lr] = av.z; sA[lc + 3][lr] = av.w;
        sB[lc + 0][lr] = wv.x; sB[lc + 1][lr] = wv.y;
        sB[lc + 2][lr] = wv.z; sB[lc + 3][lr] = wv.w;
        __syncthreads();

        #pragma unroll
        for (int kk = 0; kk < 8; kk++) {
            float a[8], b[8];
            *reinterpret_cast<float4*>(a)     = *reinterpret_cast<const float4*>(&sA[kk][tm]);
            *reinterpret_cast<float4*>(a + 4) = *reinterpret_cast<const float4*>(&sA[kk][tm + 4]);
            *reinterpret_cast<float4*>(b)     = *reinterpret_cast<const float4*>(&sB[kk][tn]);
            *reinterpret_cast<float4*>(b + 4) = *reinterpret_cast<const float4*>(&sB[kk][tn + 4]);
            #pragma unroll
            for (int i = 0; i < 8; i++)
                #pragma unroll
                for (int j = 0; j < 8; j++)
                    acc[i][j] += a[i] * b[j];
        }
    }

    if (dst < 3) {
        float* O = (dst == 0) ? g_qh : (dst == 1) ? g_kh : g_vh;
        #pragma unroll
        for (int i = 0; i < 8; i++) {
            const int m = m0 + tm + i;
            const int b = m >> 11;         // m / SEQ
            const int s = m & (SEQ - 1);
            #pragma unroll
            for (int j = 0; j < 8; j++) {
                const int n = n0 + tn + j;
                const int h  = n >> 6;
                const int dk = n & 63;
                O[(((size_t)(b * NHEAD + h) * SEQ) + s) * DK + dk] = acc[i][j];
            }
        }
    } else {
        #pragma unroll
        for (int i = 0; i < 8; i++) {
            const int m = m0 + tm + i;
            float* row = Cflat + (size_t)m * DMODEL + n0 + tn;
            #pragma unroll
            for (int j = 0; j < 8; j += 4) {
                float4 v = make_float4(acc[i][j], acc[i][j + 1], acc[i][j + 2], acc[i][j + 3]);
                *reinterpret_cast<float4*>(row + j) = v;
            }
        }
    }
}

// ----------------------------------------------------------------------------
// Flash attention: per (b,h), Q[2048,64] x K[2048,64]^T -> softmax -> x V
// Block handles 64 query rows; iterates 64-key tiles with online softmax.
// 256 threads: ty=tid/16 owns rows 4ty..4ty+3, tx=tid%16 owns cols 4tx..4tx+3.
// ----------------------------------------------------------------------------
__device__ __forceinline__ float redmax16(float v) {
    #pragma unroll
    for (int o = 8; o; o >>= 1) v = fmaxf(v, __shfl_xor_sync(0xffffffffu, v, o));
    return v;
}
__device__ __forceinline__ float redsum16(float v) {
    #pragma unroll
    for (int o = 8; o; o >>= 1) v += __shfl_xor_sync(0xffffffffu, v, o);
    return v;
}

__global__ void __launch_bounds__(256)
flash_attn(const int* __restrict__ mask) {
    __shared__ float sQ[64][64];
    __shared__ float sKt[64][68];   // [dk][key], padded
    __shared__ float sV[64][68];    // [key][dk], padded
    __shared__ float sP[64][68];    // [row][key], padded
    __shared__ int   sMask[64];

    const int tid = threadIdx.x;
    const int tx = tid & 15;
    const int ty = tid >> 4;
    const int bh = blockIdx.z * NHEAD + blockIdx.y;

    const float* Q = g_qh + ((size_t)bh * SEQ + blockIdx.x * 64) * DK;
    const float* K = g_kh + (size_t)bh * SEQ * DK;
    const float* V = g_vh + (size_t)bh * SEQ * DK;
    const int* mk = mask + blockIdx.z * SEQ;

    // Load Q tile
    #pragma unroll
    for (int i = 0; i < 4; i++) {
        int lin = i * 256 + tid;          // 1024 float4s
        int r = lin >> 4, c = (lin & 15) << 2;
        *reinterpret_cast<float4*>(&sQ[r][c]) =
            *reinterpret_cast<const float4*>(Q + r * DK + c);
    }

    float m_run[4], l_run[4], o[4][4];
    #pragma unroll
    for (int i = 0; i < 4; i++) {
        m_run[i] = -INFINITY; l_run[i] = 0.f;
        #pragma unroll
        for (int j = 0; j < 4; j++) o[i][j] = 0.f;
    }

    const float scale = 0.125f;  // 1/sqrt(64)

    for (int j0 = 0; j0 < SEQ; j0 += 64) {
        __syncthreads();  // prior PV reads (and Q load on first iter) complete
        // Load K (transposed) and V tiles
        #pragma unroll
        for (int i = 0; i < 4; i++) {
            int lin = i * 256 + tid;
            int r = lin >> 4, c = (lin & 15) << 2;
            float4 kv = *reinterpret_cast<const float4*>(K + (size_t)(j0 + r) * DK + c);
            sKt[c + 0][r] = kv.x; sKt[c + 1][r] = kv.y;
            sKt[c + 2][r] = kv.z; sKt[c + 3][r] = kv.w;
            *reinterpret_cast<float4*>(&sV[r][c]) =
                *reinterpret_cast<const float4*>(V + (size_t)(j0 + r) * DK + c);
        }
        if (tid < 64) sMask[tid] = mk[j0 + tid];
        __syncthreads();

        // Scores: s[i][j] = sum_kk Q[row][kk] * K[key][kk]
        float s[4][4];
        #pragma unroll
        for (int i = 0; i < 4; i++)
            #pragma unroll
            for (int j = 0; j < 4; j++) s[i][j] = 0.f;

        #pragma unroll
        for (int kk = 0; kk < 64; kk++) {
            float a0 = sQ[ty * 4 + 0][kk];
            float a1 = sQ[ty * 4 + 1][kk];
            float a2 = sQ[ty * 4 + 2][kk];
            float a3 = sQ[ty * 4 + 3][kk];
            float4 bv = *reinterpret_cast<const float4*>(&sKt[kk][tx * 4]);
            s[0][0] += a0 * bv.x; s[0][1] += a0 * bv.y; s[0][2] += a0 * bv.z; s[0][3] += a0 * bv.w;
            s[1][0] += a1 * bv.x; s[1][1] += a1 * bv.y; s[1][2] += a1 * bv.z; s[1][3] += a1 * bv.w;
            s[2][0] += a2 * bv.x; s[2][1] += a2 * bv.y; s[2][2] += a2 * bv.z; s[2][3] += a2 * bv.w;
            s[3][0] += a3 * bv.x; s[3][1] += a3 * bv.y; s[3][2] += a3 * bv.z; s[3][3] += a3 * bv.w;
        }

        // Scale + mask
        int mk0 = sMask[tx * 4 + 0], mk1 = sMask[tx * 4 + 1];
        int mk2 = sMask[tx * 4 + 2], mk3 = sMask[tx * 4 + 3];
        #pragma unroll
        for (int i = 0; i < 4; i++) {
            s[i][0] = (mk0 == 0) ? -1e9f : s[i][0] * scale;
            s[i][1] = (mk1 == 0) ? -1e9f : s[i][1] * scale;
            s[i][2] = (mk2 == 0) ? -1e9f : s[i][2] * scale;
            s[i][3] = (mk3 == 0) ? -1e9f : s[i][3] * scale;
        }

        // Online softmax update
        #pragma unroll
        for (int i = 0; i < 4; i++) {
            float rmax = fmaxf(fmaxf(s[i][0], s[i][1]), fmaxf(s[i][2], s[i][3]));
            rmax = redmax16(rmax);
            float mn = fmaxf(m_run[i], rmax);
            float alpha = __expf(m_run[i] - mn);
            float sum = 0.f;
            #pragma unroll
            for (int j = 0; j < 4; j++) {
                float p = __expf(s[i][j] - mn);
                s[i][j] = p;
                sum += p;
            }
            sum = redsum16(sum);
            l_run[i] = l_run[i] * alpha + sum;
            m_run[i] = mn;
            #pragma unroll
            for (int j = 0; j < 4; j++) o[i][j] *= alpha;
        }

        // Stage P to smem
        #pragma unroll
        for (int i = 0; i < 4; i++) {
            float4 pv = make_float4(s[i][0], s[i][1], s[i][2], s[i][3]);
            *reinterpret_cast<float4*>(&sP[ty * 4 + i][tx * 4]) = pv;
        }
        __syncthreads();

        // PV: o[i][j] += sum_kk P[row][kk] * V[kk][dcol]
        #pragma unroll
        for (int kk = 0; kk < 64; kk++) {
            float p0 = sP[ty * 4 + 0][kk];
            float p1 = sP[ty * 4 + 1][kk];
            float p2 = sP[ty * 4 + 2][kk];
            float p3 = sP[ty * 4 + 3][kk];
            float4 vv = *reinterpret_cast<const float4*>(&sV[kk][tx * 4]);
            o[0][0] += p0 * vv.x; o[0][1] += p0 * vv.y; o[0][2] += p0 * vv.z; o[0][3] += p0 * vv.w;
            o[1][0] += p1 * vv.x; o[1][1] += p1 * vv.y; o[1][2] += p1 * vv.z; o[1][3] += p1 * vv.w;
            o[2][0] += p2 * vv.x; o[2][1] += p2 * vv.y; o[2][2] += p2 * vv.z; o[2][3] += p2 * vv.w;
            o[3][0] += p3 * vv.x; o[3][1] += p3 * vv.y; o[3][2] += p3 * vv.z; o[3][3] += p3 * vv.w;
        }
    }

    // Epilogue: ctx[b, s, h*64 + dk]
    #pragma unroll
    for (int i = 0; i < 4; i++) {
        float inv = 1.f / l_run[i];
        int row = blockIdx.x * 64 + ty * 4 + i;
        float4 out = make_float4(o[i][0] * inv, o[i][1] * inv, o[i][2] * inv, o[i][3] * inv);
        size_t idx = ((size_t)blockIdx.z * SEQ + row) * DMODEL + blockIdx.y * DK + tx * 4;
        *reinterpret_cast<float4*>(&g_ctx[idx]) = out;
    }
}

// ----------------------------------------------------------------------------
// Launch
// ----------------------------------------------------------------------------
extern "C" void kernel_launch(void* const* d_in, const int* in_sizes, int n_in,
                              void* d_out, int out_size) {
    const float* q    = (const float*)d_in[0];
    const float* k    = (const float*)d_in[1];
    const float* v    = (const float*)d_in[2];
    const int*   mask = (const int*)  d_in[3];
    const float* Wq   = (const float*)d_in[4];
    const float* Wk   = (const float*)d_in[5];
    const float* Wv   = (const float*)d_in[6];
    const float* Wo   = (const float*)d_in[7];
    float* out = (float*)d_out;

    float* ctx_ptr = nullptr;
    cudaGetSymbolAddress((void**)&ctx_ptr, g_ctx);

    dim3 gemm_grid(DMODEL / 128, MROWS / 128);   // (8, 32)
    sgemm_nt<<<gemm_grid, 256>>>(q, Wq, nullptr, 0);
    sgemm_nt<<<gemm_grid, 256>>>(k, Wk, nullptr, 1);
    sgemm_nt<<<gemm_grid, 256>>>(v, Wv, nullptr, 2);

    dim3 fa_grid(SEQ / 64, NHEAD, BATCH);        // (32, 16, 2)
    flash_attn<<<fa_grid, 256>>>(mask);

    sgemm_nt<<<gemm_grid, 256>>>(ctx_ptr, Wo, out, 3);
}

// round 3
// speedup vs baseline: 1.7067x; 1.7067x over previous
#include <cuda_runtime.h>
#include <cuda_bf16.h>
#include <math.h>
#include <stdint.h>

// ---------------- Problem constants ----------------
#define BATCH  2
#define SEQ    2048
#define DMODEL 1024
#define NHEAD  16
#define DK     64
#define MROWS  4096        // BATCH*SEQ
#define KDIM   1024
#define KC_COUNT 16        // KDIM / 64
#define STAGES 3

// Feature gate: tcgen05 exists only in the arch-specific (sm_103a/sm_100a) target.
#if defined(__CUDA_ARCH_FEAT_SM103_ALL) || defined(__CUDA_ARCH_FEAT_SM100_ALL) || defined(__CUDA_ARCH_FEAT_SM101_ALL)
#define HAS_TC 1
#else
#define HAS_TC 0
#endif

// ---------------- Scratch (device globals; allocations forbidden) ----------
__device__ float g_qh[BATCH * NHEAD * SEQ * DK];   // [B,H,S,DK]
__device__ float g_kh[BATCH * NHEAD * SEQ * DK];
__device__ float g_vh[BATCH * NHEAD * SEQ * DK];
__device__ float g_ctx[BATCH * SEQ * DMODEL];      // [B,S,D]

// split-bf16 buffers, pre-swizzled tiled layout.
#define OFF_Q   0
#define OFF_K   4194304
#define OFF_V   8388608
#define OFF_CTX 12582912
#define OFF_WQ  16777216
#define OFF_WK  17825792
#define OFF_WV  18874368
#define OFF_WO  19922944
__device__ __nv_bfloat16 g_hi[20971520];
__device__ __nv_bfloat16 g_lo[20971520];

// ---------------- PTX helpers (used only inside HAS_TC regions) -------------
__device__ __forceinline__ uint32_t smem_u32(const void* p) {
    uint32_t a;
    asm("{ .reg .u64 t; cvta.to.shared.u64 t, %1; cvt.u32.u64 %0, t; }" : "=r"(a) : "l"(p));
    return a;
}

#define SWZ128(o) ((o) ^ (((o) >> 3) & 0x70))

#define MBARRIER_INIT(addr, cnt) \
    asm volatile("mbarrier.init.shared.b64 [%0], %1;" :: "r"(addr), "r"(cnt) : "memory")

#define MBARRIER_EXPECT_TX(addr, bytes) \
    asm volatile("mbarrier.arrive.expect_tx.shared.b64 _, [%0], %1;" :: "r"(addr), "r"(bytes) : "memory")

#define MBARRIER_WAIT_PARITY(addr, par) do {                                  \
    uint32_t _m = (addr); uint32_t _p = (par); uint32_t _d;                   \
    asm volatile("{\n\t.reg .pred p;\n\t"                                     \
        "mbarrier.try_wait.parity.acquire.cta.shared::cta.b64 p, [%1], %2;\n\t"\
        "selp.b32 %0, 1, 0, p;\n\t}" : "=r"(_d) : "r"(_m), "r"(_p) : "memory");\
    if (!_d) {                                                                \
        asm volatile("{\n\t.reg .pred P1;\n\t"                                \
        "W_%=:\n\t"                                                           \
        "mbarrier.try_wait.parity.acquire.cta.shared::cta.b64 P1, [%0], %1, 0x989680;\n\t" \
        "@P1 bra.uni D_%=;\n\t"                                               \
        "bra.uni W_%=;\n\t"                                                   \
        "D_%=:\n\t}" :: "r"(_m), "r"(_p) : "memory");                         \
    }                                                                         \
} while (0)

#define BULK_G2S(dst, src, bytes, mbar) \
    asm volatile("cp.async.bulk.shared::cluster.global.mbarrier::complete_tx::bytes [%0], [%1], %2, [%3];" \
        :: "r"(dst), "l"(src), "r"(bytes), "r"(mbar) : "memory")

#define TCGEN05_ALLOC(saddr, ncols) \
    asm volatile("tcgen05.alloc.cta_group::1.sync.aligned.shared::cta.b32 [%0], %1;" \
        :: "r"(saddr), "r"(ncols) : "memory")
#define TCGEN05_DEALLOC(tmem, ncols) \
    asm volatile("tcgen05.dealloc.cta_group::1.sync.aligned.b32 %0, %1;" :: "r"(tmem), "r"(ncols))
#define TCGEN05_RELINQ() \
    asm volatile("tcgen05.relinquish_alloc_permit.cta_group::1.sync.aligned;")
#define TCGEN05_COMMIT(mbar) \
    asm volatile("tcgen05.commit.cta_group::1.mbarrier::arrive::one.shared::cluster.b64 [%0];" \
        :: "r"(mbar) : "memory")
#define TCGEN05_FENCE_AFTER()  asm volatile("tcgen05.fence::after_thread_sync;" ::: "memory")
#define TCGEN05_FENCE_BEFORE() asm volatile("tcgen05.fence::before_thread_sync;" ::: "memory")
#define TCGEN05_WAIT_LD()      asm volatile("tcgen05.wait::ld.sync.aligned;" ::: "memory")
#define FENCE_PROXY_ASYNC()    asm volatile("fence.proxy.async.shared::cta;" ::: "memory")

#define TCGEN05_LD_X32(r, taddr) \
    asm volatile("tcgen05.ld.sync.aligned.32x32b.x32.b32 " \
        "{%0, %1, %2, %3, %4, %5, %6, %7, %8, %9, %10, %11, %12, %13, %14, %15, " \
        " %16, %17, %18, %19, %20, %21, %22, %23, %24, %25, %26, %27, %28, %29, %30, %31}, [%32];" \
        : "=r"((r)[0]), "=r"((r)[1]), "=r"((r)[2]), "=r"((r)[3]), \
          "=r"((r)[4]), "=r"((r)[5]), "=r"((r)[6]), "=r"((r)[7]), \
          "=r"((r)[8]), "=r"((r)[9]), "=r"((r)[10]), "=r"((r)[11]), \
          "=r"((r)[12]), "=r"((r)[13]), "=r"((r)[14]), "=r"((r)[15]), \
          "=r"((r)[16]), "=r"((r)[17]), "=r"((r)[18]), "=r"((r)[19]), \
          "=r"((r)[20]), "=r"((r)[21]), "=r"((r)[22]), "=r"((r)[23]), \
          "=r"((r)[24]), "=r"((r)[25]), "=r"((r)[26]), "=r"((r)[27]), \
          "=r"((r)[28]), "=r"((r)[29]), "=r"((r)[30]), "=r"((r)[31]) \
        : "r"(taddr))

// SMEM descriptor: SW128, version=1, SBO=64, LBO=1 (K-major bf16, 128B rows)
#define SMEM_DESC_BASE ((uint64_t(2) << 61) | (uint64_t(1) << 46) | (uint64_t(64) << 32) | (uint64_t(1) << 16))
#define MAKE_DESC(a) (SMEM_DESC_BASE | ((uint64_t)((a) >> 4) & 0x3FFF))

// bf16 SS MMA, cta_group::1, kind::f16, fp32 accum; M=128, N=128
#define MMA_IDESC 0x08200490u
__device__ __forceinline__ void mma_ss(uint32_t d_tmem, uint64_t a_desc, uint64_t b_desc, bool acc) {
#if HAS_TC
    uint32_t en = acc ? 1u : 0u;
    asm volatile(
        "{\n\t.reg .pred p;\n\t"
        "setp.ne.u32 p, %4, 0;\n\t"
        "tcgen05.mma.cta_group::1.kind::f16 [%0], %1, %2, %3, p;\n\t}"
        :: "r"(d_tmem), "l"(a_desc), "l"(b_desc), "r"(MMA_IDESC), "r"(en) : "memory");
#endif
}

// ---------------- Converter: fp32 -> (bf16 hi, bf16 lo), tiled+swizzled -----
// Tile (mt,kc) of [128 rows x 64 k] bf16 = 16KB contiguous at (kc*mtiles+mt)*16KB,
// internal layout = SW128-swizzled smem image (so a 1D bulk copy reproduces it).
__global__ void __launch_bounds__(256)
convert_split(const float* __restrict__ src, __nv_bfloat16* __restrict__ hi,
              __nv_bfloat16* __restrict__ lo, int mtiles) {
#if HAS_TC
    int idx = blockIdx.x * 256 + threadIdx.x;     // pair index: m*512 + kp
    float2 v = reinterpret_cast<const float2*>(src)[idx];
    int m  = idx >> 9;
    int kp = idx & 511;
    int r  = m & 127, mt = m >> 7;
    int kc = kp >> 5;
    uint32_t inoff = ((uint32_t)r << 7) + ((uint32_t)(kp & 31) << 2);
    uint32_t sw = SWZ128(inoff);
    size_t byteoff = ((size_t)(kc * mtiles + mt) << 14) + sw;

    __nv_bfloat16 h0 = __float2bfloat16(v.x);
    __nv_bfloat16 h1 = __float2bfloat16(v.y);
    __nv_bfloat16 l0 = __float2bfloat16(v.x - __bfloat162float(h0));
    __nv_bfloat16 l1 = __float2bfloat16(v.y - __bfloat162float(h1));
    *reinterpret_cast<uint32_t*>(reinterpret_cast<char*>(hi) + byteoff) =
        ((uint32_t)__bfloat16_as_ushort(h1) << 16) | (uint32_t)__bfloat16_as_ushort(h0);
    *reinterpret_cast<uint32_t*>(reinterpret_cast<char*>(lo) + byteoff) =
        ((uint32_t)__bfloat16_as_ushort(l1) << 16) | (uint32_t)__bfloat16_as_ushort(l0);
#endif
}

// ---------------- tcgen05 split-bf16 GEMM (sm_103a path) --------------------
#define TILE_B   16384
#define STAGE_B  (4 * TILE_B)
#define SM_CTRL  0
#define SM_FULL(s)  (16 + (s) * 8)
#define SM_EMPTY(s) (48 + (s) * 8)
#define SM_DONE  80
#define SM_TILES 1024
#define SM_A_HI(s) (SM_TILES + (s) * STAGE_B)
#define SM_A_LO(s) (SM_A_HI(s) + TILE_B)
#define SM_B_HI(s) (SM_A_LO(s) + TILE_B)
#define SM_B_LO(s) (SM_B_HI(s) + TILE_B)
#define GEMM_SMEM (SM_TILES + STAGES * STAGE_B)   // 197632

__global__ void __launch_bounds__(256)
gemm_bf16s(const __nv_bfloat16* __restrict__ ahi, const __nv_bfloat16* __restrict__ alo,
           const __nv_bfloat16* __restrict__ bhi, const __nv_bfloat16* __restrict__ blo,
           float* __restrict__ outflat, int dst, int mtilesA) {
#if HAS_TC
    extern __shared__ char smem[];
    const uint32_t sb = smem_u32(smem);
    const int tid = threadIdx.x, wid = tid >> 5, lid = tid & 31;
    const int mt = blockIdx.y, nt = blockIdx.x;

    if (tid == 0) {
        #pragma unroll
        for (int s = 0; s < STAGES; s++) {
            MBARRIER_INIT(sb + SM_FULL(s), 1);
            MBARRIER_INIT(sb + SM_EMPTY(s), 1);
        }
        MBARRIER_INIT(sb + SM_DONE, 1);
        FENCE_PROXY_ASYNC();
    }
    if (wid == 0) TCGEN05_ALLOC(sb + SM_CTRL, 128);
    __syncthreads();

    uint32_t tmem;
    asm volatile("ld.shared.b32 %0, [%1];" : "=r"(tmem) : "r"(sb + SM_CTRL));

    if (tid == 32) {
        // Producer: bulk-copy 4 sub-tiles per k-chunk
        int ph[STAGES] = {1, 1, 1};
        for (int kc = 0; kc < KC_COUNT; kc++) {
            int s = kc % STAGES;
            MBARRIER_WAIT_PARITY(sb + SM_EMPTY(s), ph[s]); ph[s] ^= 1;
            MBARRIER_EXPECT_TX(sb + SM_FULL(s), 4 * TILE_B);
            const char* at = (const char*)ahi + ((size_t)(kc * mtilesA + mt) << 14);
            const char* al = (const char*)alo + ((size_t)(kc * mtilesA + mt) << 14);
            const char* bt = (const char*)bhi + ((size_t)(kc * 8 + nt) << 14);
            const char* bl = (const char*)blo + ((size_t)(kc * 8 + nt) << 14);
            BULK_G2S(sb + SM_A_HI(s), at, TILE_B, sb + SM_FULL(s));
            BULK_G2S(sb + SM_A_LO(s), al, TILE_B, sb + SM_FULL(s));
            BULK_G2S(sb + SM_B_HI(s), bt, TILE_B, sb + SM_FULL(s));
            BULK_G2S(sb + SM_B_LO(s), bl, TILE_B, sb + SM_FULL(s));
        }
    } else if (tid == 0) {
        // Consumer: 12 MMAs per k-chunk (3-term split-bf16, 4 K=16 steps each)
        int ph[STAGES] = {0, 0, 0};
        bool first = true;
        for (int kc = 0; kc < KC_COUNT; kc++) {
            int s = kc % STAGES;
            MBARRIER_WAIT_PARITY(sb + SM_FULL(s), ph[s]); ph[s] ^= 1;
            uint64_t dah = MAKE_DESC(sb + SM_A_HI(s));
            uint64_t dal = MAKE_DESC(sb + SM_A_LO(s));
            uint64_t dbh = MAKE_DESC(sb + SM_B_HI(s));
            uint64_t dbl = MAKE_DESC(sb + SM_B_LO(s));
            #pragma unroll
            for (int ks = 0; ks < 4; ks++) {
                mma_ss(tmem, dah + ks * 2, dbh + ks * 2, !first); first = false;
                mma_ss(tmem, dah + ks * 2, dbl + ks * 2, true);
                mma_ss(tmem, dal + ks * 2, dbh + ks * 2, true);
            }
            TCGEN05_COMMIT(sb + SM_EMPTY(s));
        }
        TCGEN05_COMMIT(sb + SM_DONE);
    }

    // Everyone waits for all MMAs, then epilogue from TMEM
    MBARRIER_WAIT_PARITY(sb + SM_DONE, 0);
    TCGEN05_FENCE_AFTER();

    uint32_t d[64];
    const int colbase = (wid >> 2) * 64;
    TCGEN05_LD_X32(d, tmem + colbase);
    TCGEN05_LD_X32(d + 32, tmem + colbase + 32);
    TCGEN05_WAIT_LD();
    TCGEN05_FENCE_BEFORE();

    const int m = mt * 128 + (wid & 3) * 32 + lid;
    const int ng = nt * 128 + colbase;            // multiple of 64

    if (dst < 3) {
        float* O = (dst == 0) ? g_qh : (dst == 1) ? g_kh : g_vh;
        const int b = m >> 11, s = m & (SEQ - 1);
        const int h = ng >> 6;
        float* row = O + (((size_t)(b * NHEAD + h) * SEQ) + s) * DK;
        #pragma unroll
        for (int c = 0; c < 64; c += 4) {
            float4 v = make_float4(__uint_as_float(d[c]), __uint_as_float(d[c + 1]),
                                   __uint_as_float(d[c + 2]), __uint_as_float(d[c + 3]));
            *reinterpret_cast<float4*>(row + c) = v;
        }
    } else {
        float* row = outflat + (size_t)m * DMODEL + ng;
        #pragma unroll
        for (int c = 0; c < 64; c += 4) {
            float4 v = make_float4(__uint_as_float(d[c]), __uint_as_float(d[c + 1]),
                                   __uint_as_float(d[c + 2]), __uint_as_float(d[c + 3]));
            *reinterpret_cast<float4*>(row + c) = v;
        }
    }

    __syncthreads();
    if (wid == 0) {
        TCGEN05_RELINQ();
        TCGEN05_DEALLOC(tmem, 128);
    }
#endif
}

// ---------------- FFMA SGEMM fallback (plain sm_103 path) -------------------
__global__ void __launch_bounds__(256)
sgemm_nt(const float* __restrict__ A, const float* __restrict__ W,
         float* __restrict__ Cflat, int dst) {
#if !HAS_TC
    __shared__ float sA[8][128];
    __shared__ float sB[8][128];

    const int tid = threadIdx.x;
    const int lr = tid >> 1;
    const int lc = (tid & 1) << 2;
    const int m0 = blockIdx.y * 128;
    const int n0 = blockIdx.x * 128;
    const int tn = (tid & 15) << 3;
    const int tm = (tid >> 4) << 3;

    const float* Aptr = A + (size_t)(m0 + lr) * DMODEL + lc;
    const float* Wptr = W + (size_t)(n0 + lr) * DMODEL + lc;

    float acc[8][8];
    #pragma unroll
    for (int i = 0; i < 8; i++)
        #pragma unroll
        for (int j = 0; j < 8; j++) acc[i][j] = 0.f;

    for (int k0 = 0; k0 < DMODEL; k0 += 8) {
        float4 av = *reinterpret_cast<const float4*>(Aptr + k0);
        float4 wv = *reinterpret_cast<const float4*>(Wptr + k0);
        __syncthreads();
        sA[lc + 0][lr] = av.x; sA[lc + 1][lr] = av.y;
        sA[lc + 2][lr] = av.z; sA[lc + 3][lr] = av.w;
        sB[lc + 0][lr] = wv.x; sB[lc + 1][lr] = wv.y;
        sB[lc + 2][lr] = wv.z; sB[lc + 3][lr] = wv.w;
        __syncthreads();

        #pragma unroll
        for (int kk = 0; kk < 8; kk++) {
            float a[8], b[8];
            *reinterpret_cast<float4*>(a)     = *reinterpret_cast<const float4*>(&sA[kk][tm]);
            *reinterpret_cast<float4*>(a + 4) = *reinterpret_cast<const float4*>(&sA[kk][tm + 4]);
            *reinterpret_cast<float4*>(b)     = *reinterpret_cast<const float4*>(&sB[kk][tn]);
            *reinterpret_cast<float4*>(b + 4) = *reinterpret_cast<const float4*>(&sB[kk][tn + 4]);
            #pragma unroll
            for (int i = 0; i < 8; i++)
                #pragma unroll
                for (int j = 0; j < 8; j++)
                    acc[i][j] += a[i] * b[j];
        }
    }

    if (dst < 3) {
        float* O = (dst == 0) ? g_qh : (dst == 1) ? g_kh : g_vh;
        #pragma unroll
        for (int i = 0; i < 8; i++) {
            const int m = m0 + tm + i;
            const int b = m >> 11;
            const int s = m & (SEQ - 1);
            #pragma unroll
            for (int j = 0; j < 8; j++) {
                const int n = n0 + tn + j;
                const int h  = n >> 6;
                const int dk = n & 63;
                O[(((size_t)(b * NHEAD + h) * SEQ) + s) * DK + dk] = acc[i][j];
            }
        }
    } else {
        #pragma unroll
        for (int i = 0; i < 8; i++) {
            const int m = m0 + tm + i;
            float* row = Cflat + (size_t)m * DMODEL + n0 + tn;
            #pragma unroll
            for (int j = 0; j < 8; j += 4) {
                float4 v = make_float4(acc[i][j], acc[i][j + 1], acc[i][j + 2], acc[i][j + 3]);
                *reinterpret_cast<float4*>(row + j) = v;
            }
        }
    }
#endif
}

// ---------------- Flash attention (fp32 FFMA, both archs) -------------------
__device__ __forceinline__ float redmax16(float v) {
    #pragma unroll
    for (int o = 8; o; o >>= 1) v = fmaxf(v, __shfl_xor_sync(0xffffffffu, v, o));
    return v;
}
__device__ __forceinline__ float redsum16(float v) {
    #pragma unroll
    for (int o = 8; o; o >>= 1) v += __shfl_xor_sync(0xffffffffu, v, o);
    return v;
}

__global__ void __launch_bounds__(256)
flash_attn(const int* __restrict__ mask) {
    __shared__ float sQ[64][64];
    __shared__ float sKt[64][68];
    __shared__ float sV[64][68];
    __shared__ float sP[64][68];
    __shared__ int   sMask[64];

    const int tid = threadIdx.x;
    const int tx = tid & 15;
    const int ty = tid >> 4;
    const int bh = blockIdx.z * NHEAD + blockIdx.y;

    const float* Q = g_qh + ((size_t)bh * SEQ + blockIdx.x * 64) * DK;
    const float* K = g_kh + (size_t)bh * SEQ * DK;
    const float* V = g_vh + (size_t)bh * SEQ * DK;
    const int* mk = mask + blockIdx.z * SEQ;

    #pragma unroll
    for (int i = 0; i < 4; i++) {
        int lin = i * 256 + tid;
        int r = lin >> 4, c = (lin & 15) << 2;
        *reinterpret_cast<float4*>(&sQ[r][c]) =
            *reinterpret_cast<const float4*>(Q + r * DK + c);
    }

    float m_run[4], l_run[4], o[4][4];
    #pragma unroll
    for (int i = 0; i < 4; i++) {
        m_run[i] = -INFINITY; l_run[i] = 0.f;
        #pragma unroll
        for (int j = 0; j < 4; j++) o[i][j] = 0.f;
    }

    const float scale = 0.125f;

    for (int j0 = 0; j0 < SEQ; j0 += 64) {
        __syncthreads();
        #pragma unroll
        for (int i = 0; i < 4; i++) {
            int lin = i * 256 + tid;
            int r = lin >> 4, c = (lin & 15) << 2;
            float4 kv = *reinterpret_cast<const float4*>(K + (size_t)(j0 + r) * DK + c);
            sKt[c + 0][r] = kv.x; sKt[c + 1][r] = kv.y;
            sKt[c + 2][r] = kv.z; sKt[c + 3][r] = kv.w;
            *reinterpret_cast<float4*>(&sV[r][c]) =
                *reinterpret_cast<const float4*>(V + (size_t)(j0 + r) * DK + c);
        }
        if (tid < 64) sMask[tid] = mk[j0 + tid];
        __syncthreads();

        float s[4][4];
        #pragma unroll
        for (int i = 0; i < 4; i++)
            #pragma unroll
            for (int j = 0; j < 4; j++) s[i][j] = 0.f;

        #pragma unroll
        for (int kk = 0; kk < 64; kk++) {
            float a0 = sQ[ty * 4 + 0][kk];
            float a1 = sQ[ty * 4 + 1][kk];
            float a2 = sQ[ty * 4 + 2][kk];
            float a3 = sQ[ty * 4 + 3][kk];
            float4 bv = *reinterpret_cast<const float4*>(&sKt[kk][tx * 4]);
            s[0][0] += a0 * bv.x; s[0][1] += a0 * bv.y; s[0][2] += a0 * bv.z; s[0][3] += a0 * bv.w;
            s[1][0] += a1 * bv.x; s[1][1] += a1 * bv.y; s[1][2] += a1 * bv.z; s[1][3] += a1 * bv.w;
            s[2][0] += a2 * bv.x; s[2][1] += a2 * bv.y; s[2][2] += a2 * bv.z; s[2][3] += a2 * bv.w;
            s[3][0] += a3 * bv.x; s[3][1] += a3 * bv.y; s[3][2] += a3 * bv.z; s[3][3] += a3 * bv.w;
        }

        int mk0 = sMask[tx * 4 + 0], mk1 = sMask[tx * 4 + 1];
        int mk2 = sMask[tx * 4 + 2], mk3 = sMask[tx * 4 + 3];
        #pragma unroll
        for (int i = 0; i < 4; i++) {
            s[i][0] = (mk0 == 0) ? -1e9f : s[i][0] * scale;
            s[i][1] = (mk1 == 0) ? -1e9f : s[i][1] * scale;
            s[i][2] = (mk2 == 0) ? -1e9f : s[i][2] * scale;
            s[i][3] = (mk3 == 0) ? -1e9f : s[i][3] * scale;
        }

        #pragma unroll
        for (int i = 0; i < 4; i++) {
            float rmax = fmaxf(fmaxf(s[i][0], s[i][1]), fmaxf(s[i][2], s[i][3]));
            rmax = redmax16(rmax);
            float mn = fmaxf(m_run[i], rmax);
            float alpha = __expf(m_run[i] - mn);
            float sum = 0.f;
            #pragma unroll
            for (int j = 0; j < 4; j++) {
                float p = __expf(s[i][j] - mn);
                s[i][j] = p;
                sum += p;
            }
            sum = redsum16(sum);
            l_run[i] = l_run[i] * alpha + sum;
            m_run[i] = mn;
            #pragma unroll
            for (int j = 0; j < 4; j++) o[i][j] *= alpha;
        }

        #pragma unroll
        for (int i = 0; i < 4; i++) {
            float4 pv = make_float4(s[i][0], s[i][1], s[i][2], s[i][3]);
            *reinterpret_cast<float4*>(&sP[ty * 4 + i][tx * 4]) = pv;
        }
        __syncthreads();

        #pragma unroll
        for (int kk = 0; kk < 64; kk++) {
            float p0 = sP[ty * 4 + 0][kk];
            float p1 = sP[ty * 4 + 1][kk];
            float p2 = sP[ty * 4 + 2][kk];
            float p3 = sP[ty * 4 + 3][kk];
            float4 vv = *reinterpret_cast<const float4*>(&sV[kk][tx * 4]);
            o[0][0] += p0 * vv.x; o[0][1] += p0 * vv.y; o[0][2] += p0 * vv.z; o[0][3] += p0 * vv.w;
            o[1][0] += p1 * vv.x; o[1][1] += p1 * vv.y; o[1][2] += p1 * vv.z; o[1][3] += p1 * vv.w;
            o[2][0] += p2 * vv.x; o[2][1] += p2 * vv.y; o[2][2] += p2 * vv.z; o[2][3] += p2 * vv.w;
            o[3][0] += p3 * vv.x; o[3][1] += p3 * vv.y; o[3][2] += p3 * vv.z; o[3][3] += p3 * vv.w;
        }
    }

    #pragma unroll
    for (int i = 0; i < 4; i++) {
        float inv = 1.f / l_run[i];
        int row = blockIdx.x * 64 + ty * 4 + i;
        float4 out = make_float4(o[i][0] * inv, o[i][1] * inv, o[i][2] * inv, o[i][3] * inv);
        size_t idx = ((size_t)blockIdx.z * SEQ + row) * DMODEL + blockIdx.y * DK + tx * 4;
        *reinterpret_cast<float4*>(&g_ctx[idx]) = out;
    }
}

// ---------------- Launch -----------------------------------------------------
// Both implementation families are launched; exactly one does work depending on
// which cubin (sm_103a vs sm_103) the driver selected for this module. The
// inactive family's kernels return immediately.
extern "C" void kernel_launch(void* const* d_in, const int* in_sizes, int n_in,
                              void* d_out, int out_size) {
    const float* q    = (const float*)d_in[0];
    const float* k    = (const float*)d_in[1];
    const float* v    = (const float*)d_in[2];
    const int*   mask = (const int*)  d_in[3];
    const float* Wq   = (const float*)d_in[4];
    const float* Wk   = (const float*)d_in[5];
    const float* Wv   = (const float*)d_in[6];
    const float* Wo   = (const float*)d_in[7];
    float* out = (float*)d_out;

    float* ctx_ptr = nullptr;
    __nv_bfloat16 *hi_ptr = nullptr, *lo_ptr = nullptr;
    cudaGetSymbolAddress((void**)&ctx_ptr, g_ctx);
    cudaGetSymbolAddress((void**)&hi_ptr, g_hi);
    cudaGetSymbolAddress((void**)&lo_ptr, g_lo);

    cudaFuncSetAttribute(gemm_bf16s, cudaFuncAttributeMaxDynamicSharedMemorySize, GEMM_SMEM);

    dim3 ggrid(8, 32);  // (N/128, M/128)
    dim3 fa_grid(SEQ / 64, NHEAD, BATCH);

    // --- TC path: converters (no-ops on plain sm_103) ---
    convert_split<<<MROWS * 2, 256>>>(q,  hi_ptr + OFF_Q,  lo_ptr + OFF_Q,  32);
    convert_split<<<MROWS * 2, 256>>>(k,  hi_ptr + OFF_K,  lo_ptr + OFF_K,  32);
    convert_split<<<MROWS * 2, 256>>>(v,  hi_ptr + OFF_V,  lo_ptr + OFF_V,  32);
    convert_split<<<2048, 256>>>(Wq, hi_ptr + OFF_WQ, lo_ptr + OFF_WQ, 8);
    convert_split<<<2048, 256>>>(Wk, hi_ptr + OFF_WK, lo_ptr + OFF_WK, 8);
    convert_split<<<2048, 256>>>(Wv, hi_ptr + OFF_WV, lo_ptr + OFF_WV, 8);
    convert_split<<<2048, 256>>>(Wo, hi_ptr + OFF_WO, lo_ptr + OFF_WO, 8);

    // --- QKV projections (one family is active) ---
    gemm_bf16s<<<ggrid, 256, GEMM_SMEM>>>(hi_ptr + OFF_Q, lo_ptr + OFF_Q,
                                          hi_ptr + OFF_WQ, lo_ptr + OFF_WQ, nullptr, 0, 32);
    gemm_bf16s<<<ggrid, 256, GEMM_SMEM>>>(hi_ptr + OFF_K, lo_ptr + OFF_K,
                                          hi_ptr + OFF_WK, lo_ptr + OFF_WK, nullptr, 1, 32);
    gemm_bf16s<<<ggrid, 256, GEMM_SMEM>>>(hi_ptr + OFF_V, lo_ptr + OFF_V,
                                          hi_ptr + OFF_WV, lo_ptr + OFF_WV, nullptr, 2, 32);
    sgemm_nt<<<ggrid, 256>>>(q, Wq, nullptr, 0);
    sgemm_nt<<<ggrid, 256>>>(k, Wk, nullptr, 1);
    sgemm_nt<<<ggrid, 256>>>(v, Wv, nullptr, 2);

    // --- Attention ---
    flash_attn<<<fa_grid, 256>>>(mask);

    // --- Output projection ---
    convert_split<<<MROWS * 2, 256>>>(ctx_ptr, hi_ptr + OFF_CTX, lo_ptr + OFF_CTX, 32);
    gemm_bf16s<<<ggrid, 256, GEMM_SMEM>>>(hi_ptr + OFF_CTX, lo_ptr + OFF_CTX,
                                          hi_ptr + OFF_WO, lo_ptr + OFF_WO, out, 3, 32);
    sgemm_nt<<<ggrid, 256>>>(ctx_ptr, Wo, out, 3);
}

// round 5
// speedup vs baseline: 4.4968x; 2.6348x over previous
#include <cuda_runtime.h>
#include <cuda_bf16.h>
#include <math.h>
#include <stdint.h>

// ---------------- Problem constants ----------------
#define BATCH  2
#define SEQ    2048
#define DMODEL 1024
#define NHEAD  16
#define DK     64
#define MROWS  4096        // BATCH*SEQ
#define KDIM   1024
#define KC_COUNT 16        // KDIM / 64
#define STAGES 3

// Feature gate: tcgen05 exists only in the arch-specific (sm_103a/sm_100a) target.
#if defined(__CUDA_ARCH_FEAT_SM103_ALL) || defined(__CUDA_ARCH_FEAT_SM100_ALL) || defined(__CUDA_ARCH_FEAT_SM101_ALL)
#define HAS_TC 1
#else
#define HAS_TC 0
#endif

// ---------------- Scratch (device globals; allocations forbidden) ----------
__device__ float g_qh[BATCH * NHEAD * SEQ * DK];   // fallback path only
__device__ float g_kh[BATCH * NHEAD * SEQ * DK];
__device__ float g_vh[BATCH * NHEAD * SEQ * DK];
__device__ float g_ctx[BATCH * SEQ * DMODEL];      // [B,S,D]

// split-bf16 GEMM input buffers, pre-swizzled tiled layout.
#define OFF_Q   0
#define OFF_K   4194304
#define OFF_V   8388608
#define OFF_CTX 12582912
#define OFF_WQ  16777216
#define OFF_WK  17825792
#define OFF_WV  18874368
#define OFF_WO  19922944
__device__ __nv_bfloat16 g_hi[20971520];
__device__ __nv_bfloat16 g_lo[20971520];

// Attention operand tiles (written by projection GEMM epilogues):
// Q,K: per (bh, stile) [128 seq x 64 dk] bf16 SW128 tiles (16KB each).
// V:   per (bh, stile) transposed [64 dk x 128 keys] blocked-atom SW128 tiles.
__device__ __align__(1024) __nv_bfloat16 g_tqh[4194304];
__device__ __align__(1024) __nv_bfloat16 g_tql[4194304];
__device__ __align__(1024) __nv_bfloat16 g_tkh[4194304];
__device__ __align__(1024) __nv_bfloat16 g_tkl[4194304];
__device__ __align__(1024) __nv_bfloat16 g_tvh[4194304];
__device__ __align__(1024) __nv_bfloat16 g_tvl[4194304];

// ---------------- PTX helpers (used only inside HAS_TC regions) -------------
__device__ __forceinline__ uint32_t smem_u32(const void* p) {
    uint32_t a;
    asm("{ .reg .u64 t; cvta.to.shared.u64 t, %1; cvt.u32.u64 %0, t; }" : "=r"(a) : "l"(p));
    return a;
}

#define SWZ128(o) ((o) ^ (((o) >> 3) & 0x70))

#define MBARRIER_INIT(addr, cnt) \
    asm volatile("mbarrier.init.shared.b64 [%0], %1;" :: "r"(addr), "r"(cnt) : "memory")

#define MBARRIER_EXPECT_TX(addr, bytes) \
    asm volatile("mbarrier.arrive.expect_tx.shared.b64 _, [%0], %1;" :: "r"(addr), "r"(bytes) : "memory")

#define MBARRIER_WAIT_PARITY(addr, par) do {                                  \
    uint32_t _m = (addr); uint32_t _p = (par); uint32_t _d;                   \
    asm volatile("{\n\t.reg .pred p;\n\t"                                     \
        "mbarrier.try_wait.parity.acquire.cta.shared::cta.b64 p, [%1], %2;\n\t"\
        "selp.b32 %0, 1, 0, p;\n\t}" : "=r"(_d) : "r"(_m), "r"(_p) : "memory");\
    if (!_d) {                                                                \
        asm volatile("{\n\t.reg .pred P1;\n\t"                                \
        "W_%=:\n\t"                                                           \
        "mbarrier.try_wait.parity.acquire.cta.shared::cta.b64 P1, [%0], %1, 0x989680;\n\t" \
        "@P1 bra.uni D_%=;\n\t"                                               \
        "bra.uni W_%=;\n\t"                                                   \
        "D_%=:\n\t}" :: "r"(_m), "r"(_p) : "memory");                         \
    }                                                                         \
} while (0)

#define BULK_G2S(dst, src, bytes, mbar) \
    asm volatile("cp.async.bulk.shared::cluster.global.mbarrier::complete_tx::bytes [%0], [%1], %2, [%3];" \
        :: "r"(dst), "l"(src), "r"(bytes), "r"(mbar) : "memory")

#define TCGEN05_ALLOC(saddr, ncols) \
    asm volatile("tcgen05.alloc.cta_group::1.sync.aligned.shared::cta.b32 [%0], %1;" \
        :: "r"(saddr), "r"(ncols) : "memory")
#define TCGEN05_DEALLOC(tmem, ncols) \
    asm volatile("tcgen05.dealloc.cta_group::1.sync.aligned.b32 %0, %1;" :: "r"(tmem), "r"(ncols))
#define TCGEN05_RELINQ() \
    asm volatile("tcgen05.relinquish_alloc_permit.cta_group::1.sync.aligned;")
#define TCGEN05_COMMIT(mbar) \
    asm volatile("tcgen05.commit.cta_group::1.mbarrier::arrive::one.shared::cluster.b64 [%0];" \
        :: "r"(mbar) : "memory")
#define TCGEN05_FENCE_AFTER()  asm volatile("tcgen05.fence::after_thread_sync;" ::: "memory")
#define TCGEN05_FENCE_BEFORE() asm volatile("tcgen05.fence::before_thread_sync;" ::: "memory")
#define TCGEN05_WAIT_LD()      asm volatile("tcgen05.wait::ld.sync.aligned;" ::: "memory")
#define TCGEN05_WAIT_ST()      asm volatile("tcgen05.wait::st.sync.aligned;" ::: "memory")
#define FENCE_PROXY_ASYNC()    asm volatile("fence.proxy.async.shared::cta;" ::: "memory")

#define TCGEN05_LD_X32(r, taddr) \
    asm volatile("tcgen05.ld.sync.aligned.32x32b.x32.b32 " \
        "{%0, %1, %2, %3, %4, %5, %6, %7, %8, %9, %10, %11, %12, %13, %14, %15, " \
        " %16, %17, %18, %19, %20, %21, %22, %23, %24, %25, %26, %27, %28, %29, %30, %31}, [%32];" \
        : "=r"((r)[0]), "=r"((r)[1]), "=r"((r)[2]), "=r"((r)[3]), \
          "=r"((r)[4]), "=r"((r)[5]), "=r"((r)[6]), "=r"((r)[7]), \
          "=r"((r)[8]), "=r"((r)[9]), "=r"((r)[10]), "=r"((r)[11]), \
          "=r"((r)[12]), "=r"((r)[13]), "=r"((r)[14]), "=r"((r)[15]), \
          "=r"((r)[16]), "=r"((r)[17]), "=r"((r)[18]), "=r"((r)[19]), \
          "=r"((r)[20]), "=r"((r)[21]), "=r"((r)[22]), "=r"((r)[23]), \
          "=r"((r)[24]), "=r"((r)[25]), "=r"((r)[26]), "=r"((r)[27]), \
          "=r"((r)[28]), "=r"((r)[29]), "=r"((r)[30]), "=r"((r)[31]) \
        : "r"(taddr))

#define TCGEN05_ST_X32(taddr, r) \
    asm volatile("tcgen05.st.sync.aligned.32x32b.x32.b32 [%0], " \
        "{%1, %2, %3, %4, %5, %6, %7, %8, %9, %10, %11, %12, %13, %14, %15, %16, " \
        " %17, %18, %19, %20, %21, %22, %23, %24, %25, %26, %27, %28, %29, %30, %31, %32};" \
        :: "r"(taddr), \
           "r"((r)[0]), "r"((r)[1]), "r"((r)[2]), "r"((r)[3]), \
           "r"((r)[4]), "r"((r)[5]), "r"((r)[6]), "r"((r)[7]), \
           "r"((r)[8]), "r"((r)[9]), "r"((r)[10]), "r"((r)[11]), \
           "r"((r)[12]), "r"((r)[13]), "r"((r)[14]), "r"((r)[15]), \
           "r"((r)[16]), "r"((r)[17]), "r"((r)[18]), "r"((r)[19]), \
           "r"((r)[20]), "r"((r)[21]), "r"((r)[22]), "r"((r)[23]), \
           "r"((r)[24]), "r"((r)[25]), "r"((r)[26]), "r"((r)[27]), \
           "r"((r)[28]), "r"((r)[29]), "r"((r)[30]), "r"((r)[31]) \
        : "memory")

// SMEM descriptor: SW128, version=1, SBO=64, LBO=1 (K-major bf16, 128B rows)
#define SMEM_DESC_BASE ((uint64_t(2) << 61) | (uint64_t(1) << 46) | (uint64_t(64) << 32) | (uint64_t(1) << 16))
#define MAKE_DESC(a) (SMEM_DESC_BASE | ((uint64_t)((a) >> 4) & 0x3FFF))

// bf16 MMA idescs: dtype F32, atype/btype BF16
#define IDESC_N128 0x08200490u   // M=128, N=128
#define IDESC_N64  0x08100490u   // M=128, N=64

__device__ __forceinline__ void mma_ss(uint32_t d_tmem, uint64_t a_desc, uint64_t b_desc,
                                       uint32_t idesc, bool acc) {
#if HAS_TC
    uint32_t en = acc ? 1u : 0u;
    asm volatile(
        "{\n\t.reg .pred p;\n\t"
        "setp.ne.u32 p, %4, 0;\n\t"
        "tcgen05.mma.cta_group::1.kind::f16 [%0], %1, %2, %3, p;\n\t}"
        :: "r"(d_tmem), "l"(a_desc), "l"(b_desc), "r"(idesc), "r"(en) : "memory");
#endif
}
__device__ __forceinline__ void mma_ts(uint32_t d_tmem, uint32_t a_tmem, uint64_t b_desc,
                                       uint32_t idesc, bool acc) {
#if HAS_TC
    uint32_t en = acc ? 1u : 0u;
    asm volatile(
        "{\n\t.reg .pred p;\n\t"
        "setp.ne.u32 p, %4, 0;\n\t"
        "tcgen05.mma.cta_group::1.kind::f16 [%0], [%1], %2, %3, p;\n\t}"
        :: "r"(d_tmem), "r"(a_tmem), "l"(b_desc), "r"(idesc), "r"(en) : "memory");
#endif
}

__device__ __forceinline__ float ex2f(float x) {
    float y;
    asm("ex2.approx.f32 %0, %1;" : "=f"(y) : "f"(x));
    return y;
}

// ---------------- Converter: fp32 -> (bf16 hi, bf16 lo), tiled+swizzled -----
__global__ void __launch_bounds__(256)
convert_split(const float* __restrict__ src, __nv_bfloat16* __restrict__ hi,
              __nv_bfloat16* __restrict__ lo, int mtiles) {
#if HAS_TC
    int idx = blockIdx.x * 256 + threadIdx.x;     // pair index: m*512 + kp
    float2 v = reinterpret_cast<const float2*>(src)[idx];
    int m  = idx >> 9;
    int kp = idx & 511;
    int r  = m & 127, mt = m >> 7;
    int kc = kp >> 5;
    uint32_t inoff = ((uint32_t)r << 7) + ((uint32_t)(kp & 31) << 2);
    uint32_t sw = SWZ128(inoff);
    size_t byteoff = ((size_t)(kc * mtiles + mt) << 14) + sw;

    __nv_bfloat16 h0 = __float2bfloat16(v.x);
    __nv_bfloat16 h1 = __float2bfloat16(v.y);
    __nv_bfloat16 l0 = __float2bfloat16(v.x - __bfloat162float(h0));
    __nv_bfloat16 l1 = __float2bfloat16(v.y - __bfloat162float(h1));
    *reinterpret_cast<uint32_t*>(reinterpret_cast<char*>(hi) + byteoff) =
        ((uint32_t)__bfloat16_as_ushort(h1) << 16) | (uint32_t)__bfloat16_as_ushort(h0);
    *reinterpret_cast<uint32_t*>(reinterpret_cast<char*>(lo) + byteoff) =
        ((uint32_t)__bfloat16_as_ushort(l1) << 16) | (uint32_t)__bfloat16_as_ushort(l0);
#endif
}

// ---------------- tcgen05 split-bf16 GEMM (sm_103a path) --------------------
#define TILE_B   16384
#define STAGE_B  (4 * TILE_B)
#define SM_CTRL  0
#define SM_FULL(s)  (16 + (s) * 8)
#define SM_EMPTY(s) (48 + (s) * 8)
#define SM_DONE  80
#define SM_TILES 1024
#define SM_A_HI(s) (SM_TILES + (s) * STAGE_B)
#define SM_A_LO(s) (SM_A_HI(s) + TILE_B)
#define SM_B_HI(s) (SM_A_LO(s) + TILE_B)
#define SM_B_LO(s) (SM_B_HI(s) + TILE_B)
#define GEMM_SMEM (SM_TILES + STAGES * STAGE_B)   // 197632

__global__ void __launch_bounds__(256)
gemm_bf16s(const __nv_bfloat16* __restrict__ ahi, const __nv_bfloat16* __restrict__ alo,
           const __nv_bfloat16* __restrict__ bhi, const __nv_bfloat16* __restrict__ blo,
           float* __restrict__ outflat, int dst, int mtilesA) {
#if HAS_TC
    extern __shared__ char smem[];
    const uint32_t sb = smem_u32(smem);
    const int tid = threadIdx.x, wid = tid >> 5, lid = tid & 31;
    const int mt = blockIdx.y, nt = blockIdx.x;

    if (tid == 0) {
        #pragma unroll
        for (int s = 0; s < STAGES; s++) {
            MBARRIER_INIT(sb + SM_FULL(s), 1);
            MBARRIER_INIT(sb + SM_EMPTY(s), 1);
        }
        MBARRIER_INIT(sb + SM_DONE, 1);
        FENCE_PROXY_ASYNC();
    }
    if (wid == 0) TCGEN05_ALLOC(sb + SM_CTRL, 128);
    __syncthreads();

    uint32_t tmem;
    asm volatile("ld.shared.b32 %0, [%1];" : "=r"(tmem) : "r"(sb + SM_CTRL));

    if (tid == 32) {
        int ph[STAGES] = {1, 1, 1};
        for (int kc = 0; kc < KC_COUNT; kc++) {
            int s = kc % STAGES;
            MBARRIER_WAIT_PARITY(sb + SM_EMPTY(s), ph[s]); ph[s] ^= 1;
            MBARRIER_EXPECT_TX(sb + SM_FULL(s), 4 * TILE_B);
            const char* at = (const char*)ahi + ((size_t)(kc * mtilesA + mt) << 14);
            const char* al = (const char*)alo + ((size_t)(kc * mtilesA + mt) << 14);
            const char* bt = (const char*)bhi + ((size_t)(kc * 8 + nt) << 14);
            const char* bl = (const char*)blo + ((size_t)(kc * 8 + nt) << 14);
            BULK_G2S(sb + SM_A_HI(s), at, TILE_B, sb + SM_FULL(s));
            BULK_G2S(sb + SM_A_LO(s), al, TILE_B, sb + SM_FULL(s));
            BULK_G2S(sb + SM_B_HI(s), bt, TILE_B, sb + SM_FULL(s));
            BULK_G2S(sb + SM_B_LO(s), bl, TILE_B, sb + SM_FULL(s));
        }
    } else if (tid == 0) {
        int ph[STAGES] = {0, 0, 0};
        bool first = true;
        for (int kc = 0; kc < KC_COUNT; kc++) {
            int s = kc % STAGES;
            MBARRIER_WAIT_PARITY(sb + SM_FULL(s), ph[s]); ph[s] ^= 1;
            uint64_t dah = MAKE_DESC(sb + SM_A_HI(s));
            uint64_t dal = MAKE_DESC(sb + SM_A_LO(s));
            uint64_t dbh = MAKE_DESC(sb + SM_B_HI(s));
            uint64_t dbl = MAKE_DESC(sb + SM_B_LO(s));
            #pragma unroll
            for (int ks = 0; ks < 4; ks++) {
                mma_ss(tmem, dah + ks * 2, dbh + ks * 2, IDESC_N128, !first); first = false;
                mma_ss(tmem, dah + ks * 2, dbl + ks * 2, IDESC_N128, true);
                mma_ss(tmem, dal + ks * 2, dbh + ks * 2, IDESC_N128, true);
            }
            TCGEN05_COMMIT(sb + SM_EMPTY(s));
        }
        TCGEN05_COMMIT(sb + SM_DONE);
    }

    MBARRIER_WAIT_PARITY(sb + SM_DONE, 0);
    TCGEN05_FENCE_AFTER();

    uint32_t d[64];
    const int colbase = (wid >> 2) * 64;
    TCGEN05_LD_X32(d, tmem + colbase);
    TCGEN05_LD_X32(d + 32, tmem + colbase + 32);
    TCGEN05_WAIT_LD();
    TCGEN05_FENCE_BEFORE();

    const int m = mt * 128 + (wid & 3) * 32 + lid;
    const int ng = nt * 128 + colbase;            // multiple of 64

    if (dst < 3) {
        // Write split-bf16 attention operand tiles directly.
        const int b = m >> 11, sq = m & (SEQ - 1);
        const int h = ng >> 6;
        const int tile = (b * NHEAD + h) * 16 + (sq >> 7);
        const int rr = sq & 127;
        if (dst == 0 || dst == 1) {
            char* hb = (char*)(dst == 0 ? g_tqh : g_tkh) + ((size_t)tile << 14);
            char* lb = (char*)(dst == 0 ? g_tql : g_tkl) + ((size_t)tile << 14);
            #pragma unroll
            for (int c = 0; c < 64; c += 2) {
                float v0 = __uint_as_float(d[c]), v1 = __uint_as_float(d[c + 1]);
                __nv_bfloat16 h0 = __float2bfloat16(v0), h1 = __float2bfloat16(v1);
                __nv_bfloat16 l0 = __float2bfloat16(v0 - __bfloat162float(h0));
                __nv_bfloat16 l1 = __float2bfloat16(v1 - __bfloat162float(h1));
                uint32_t off = SWZ128((uint32_t)(rr * 128 + c * 2));
                *(uint32_t*)(hb + off) =
                    ((uint32_t)__bfloat16_as_ushort(h1) << 16) | (uint32_t)__bfloat16_as_ushort(h0);
                *(uint32_t*)(lb + off) =
                    ((uint32_t)__bfloat16_as_ushort(l1) << 16) | (uint32_t)__bfloat16_as_ushort(l0);
            }
        } else {
            // V transposed tile: [64 d rows x 128 keys] blocked-atom SW128.
            char* hb = (char*)g_tvh + ((size_t)tile << 14);
            char* lb = (char*)g_tvl + ((size_t)tile << 14);
            const int kin = rr;
            #pragma unroll
            for (int c = 0; c < 64; c++) {
                float v0 = __uint_as_float(d[c]);
                __nv_bfloat16 h0 = __float2bfloat16(v0);
                __nv_bfloat16 l0 = __float2bfloat16(v0 - __bfloat162float(h0));
                uint32_t bo = (uint32_t)(((c >> 3) + (kin >> 6) * 8) * 1024 +
                                         (c & 7) * 128 + (kin & 63) * 2);
                uint32_t off = SWZ128(bo);
                *(__nv_bfloat16*)(hb + off) = h0;
                *(__nv_bfloat16*)(lb + off) = l0;
            }
        }
    } else {
        float* row = outflat + (size_t)m * DMODEL + ng;
        #pragma unroll
        for (int c = 0; c < 64; c += 4) {
            float4 v = make_float4(__uint_as_float(d[c]), __uint_as_float(d[c + 1]),
                                   __uint_as_float(d[c + 2]), __uint_as_float(d[c + 3]));
            *reinterpret_cast<float4*>(row + c) = v;
        }
    }

    __syncthreads();
    if (wid == 0) {
        TCGEN05_RELINQ();
        TCGEN05_DEALLOC(tmem, 128);
    }
#endif
}

// ---------------- tcgen05 flash attention (sm_103a path) --------------------
// One CTA per (bh, 128-query tile). 256 threads = 8 warps.
// Strictly serialized barrier protocol: every commit precedes its wait within
// the same iteration; the end-of-iteration OD wait establishes all invariants
// (stage free, O stable) for the next iteration without further barriers.
#define F_TM     0
#define F_FULL(s) (16 + (s) * 8)
#define F_SD(s)   (32 + (s) * 8)
#define F_OD(s)   (48 + (s) * 8)
#define F_QFULL  64
#define F_REDA   256
#define F_REDB   1280
#define F_MASK   2304
#define F_QH     4096
#define F_QL     20480
#define F_STG    36864
#define F_STGSZ  65536
#define FLASH_SMEM 167936
#define TC_S   0
#define TC_O   128
#define TC_PH  192
#define TC_PL  256

__global__ void __launch_bounds__(256)
flash_tc(const int* __restrict__ mask) {
#if HAS_TC
    extern __shared__ char fsm[];
    const uint32_t sb = smem_u32(fsm);
    const int tid = threadIdx.x;
    const int lane = tid & 31;
    const int sp = (tid >> 5) & 3;        // subpartition (rows sp*32+lane)
    const int ch = tid >> 7;              // column half
    const int r = sp * 32 + lane;
    const int bh = blockIdx.z * NHEAD + blockIdx.y;
    const int qt = blockIdx.x;

    if (tid == 0) {
        MBARRIER_INIT(sb + F_FULL(0), 1);
        MBARRIER_INIT(sb + F_FULL(1), 1);
        MBARRIER_INIT(sb + F_SD(0), 1);
        MBARRIER_INIT(sb + F_SD(1), 1);
        MBARRIER_INIT(sb + F_OD(0), 1);
        MBARRIER_INIT(sb + F_OD(1), 1);
        MBARRIER_INIT(sb + F_QFULL, 1);
        FENCE_PROXY_ASYNC();
    }
    if ((tid >> 5) == 0) TCGEN05_ALLOC(sb + F_TM, 512);
    __syncthreads();

    uint32_t tmem;
    asm volatile("ld.shared.b32 %0, [%1];" : "=r"(tmem) : "r"(sb + F_TM));

    // Q tile + stage 0 loads.
    if (tid == 0) {
        const size_t qoff = ((size_t)(bh * 16 + qt)) << 14;
        MBARRIER_EXPECT_TX(sb + F_QFULL, 32768);
        BULK_G2S(sb + F_QH, (const char*)g_tqh + qoff, TILE_B, sb + F_QFULL);
        BULK_G2S(sb + F_QL, (const char*)g_tql + qoff, TILE_B, sb + F_QFULL);
        const size_t koff = ((size_t)(bh * 16 + 0)) << 14;
        MBARRIER_EXPECT_TX(sb + F_FULL(0), 4 * TILE_B);
        BULK_G2S(sb + F_STG + 0,     (const char*)g_tkh + koff, TILE_B, sb + F_FULL(0));
        BULK_G2S(sb + F_STG + 16384, (const char*)g_tkl + koff, TILE_B, sb + F_FULL(0));
        BULK_G2S(sb + F_STG + 32768, (const char*)g_tvh + koff, TILE_B, sb + F_FULL(0));
        BULK_G2S(sb + F_STG + 49152, (const char*)g_tvl + koff, TILE_B, sb + F_FULL(0));
    }

    float m_run = -INFINITY, l_run = 0.f;
    const float cs = 0.125f * 1.4426950408889634f;   // scale * log2(e)
    const int* mk = mask + blockIdx.z * SEQ;
    float* redA = (float*)(fsm + F_REDA);
    float* redB = (float*)(fsm + F_REDB);
    int* smk = (int*)(fsm + F_MASK);

    for (int kt = 0; kt < 16; kt++) {
        const int s = kt & 1;
        const int p2 = (kt >> 1) & 1;
        const uint32_t stg = sb + F_STG + s * F_STGSZ;

        if (tid == 0) {
            // Prefetch kt+1 into the other stage. That stage is provably free:
            // all threads waited OD(kt-1) at the end of the previous iteration.
            if (kt < 15) {
                const int s1 = s ^ 1;
                const size_t koff = ((size_t)(bh * 16 + kt + 1)) << 14;
                MBARRIER_EXPECT_TX(sb + F_FULL(s1), 4 * TILE_B);
                const uint32_t d1 = sb + F_STG + s1 * F_STGSZ;
                BULK_G2S(d1 + 0,     (const char*)g_tkh + koff, TILE_B, sb + F_FULL(s1));
                BULK_G2S(d1 + 16384, (const char*)g_tkl + koff, TILE_B, sb + F_FULL(s1));
                BULK_G2S(d1 + 32768, (const char*)g_tvh + koff, TILE_B, sb + F_FULL(s1));
                BULK_G2S(d1 + 49152, (const char*)g_tvl + koff, TILE_B, sb + F_FULL(s1));
            }
            if (kt == 0) MBARRIER_WAIT_PARITY(sb + F_QFULL, 0);
            MBARRIER_WAIT_PARITY(sb + F_FULL(s), p2);
            // MMA1: S = Q @ K^T (3-term split-bf16)
            const uint64_t dqh = MAKE_DESC(sb + F_QH);
            const uint64_t dql = MAKE_DESC(sb + F_QL);
            const uint64_t dkh = MAKE_DESC(stg);
            const uint64_t dkl = MAKE_DESC(stg + 16384);
            #pragma unroll
            for (int ks = 0; ks < 4; ks++)
                mma_ss(tmem + TC_S, dqh + ks * 2, dkh + ks * 2, IDESC_N128, ks > 0);
            #pragma unroll
            for (int ks = 0; ks < 4; ks++)
                mma_ss(tmem + TC_S, dqh + ks * 2, dkl + ks * 2, IDESC_N128, true);
            #pragma unroll
            for (int ks = 0; ks < 4; ks++)
                mma_ss(tmem + TC_S, dql + ks * 2, dkh + ks * 2, IDESC_N128, true);
            TCGEN05_COMMIT(sb + F_SD(s));
        }

        if (tid < 128) smk[tid] = mk[kt * 128 + tid];

        // All threads: wait MMA1, read S.
        MBARRIER_WAIT_PARITY(sb + F_SD(s), p2);
        TCGEN05_FENCE_AFTER();

        uint32_t sr[64];
        TCGEN05_LD_X32(sr, tmem + TC_S + ch * 64);
        TCGEN05_LD_X32(sr + 32, tmem + TC_S + ch * 64 + 32);
        TCGEN05_WAIT_LD();
        __syncthreads();   // sMask visible

        float t[64];
        float rmax = -INFINITY;
        const int* mcol = smk + ch * 64;
        #pragma unroll
        for (int j = 0; j < 64; j++) {
            float v = __uint_as_float(sr[j]) * cs;
            t[j] = (mcol[j] == 0) ? -1.8033689e8f : v;
            rmax = fmaxf(rmax, t[j]);
        }
        redA[ch * 128 + r] = rmax;
        __syncthreads();
        const float om = redA[(1 - ch) * 128 + r];
        const float mn = fmaxf(m_run, fmaxf(rmax, om));
        const float alpha = ex2f(m_run - mn);

        float sum = 0.f;
        uint32_t ph[32], pl[32];
        #pragma unroll
        for (int j = 0; j < 32; j++) {
            float p0 = ex2f(t[2 * j] - mn);
            float p1 = ex2f(t[2 * j + 1] - mn);
            sum += p0 + p1;
            __nv_bfloat16 h0 = __float2bfloat16(p0);
            __nv_bfloat16 h1 = __float2bfloat16(p1);
            __nv_bfloat16 l0 = __float2bfloat16(p0 - __bfloat162float(h0));
            __nv_bfloat16 l1 = __float2bfloat16(p1 - __bfloat162float(h1));
            ph[j] = ((uint32_t)__bfloat16_as_ushort(h1) << 16) | (uint32_t)__bfloat16_as_ushort(h0);
            pl[j] = ((uint32_t)__bfloat16_as_ushort(l1) << 16) | (uint32_t)__bfloat16_as_ushort(l0);
        }
        redB[ch * 128 + r] = sum;

        // Store P to TMEM.
        TCGEN05_ST_X32(tmem + TC_PH + ch * 32, ph);
        TCGEN05_ST_X32(tmem + TC_PL + ch * 32, pl);

        // O rescale in TMEM. MMA2(kt-1) completed (OD wait at end of previous
        // iteration by ALL threads), so no barrier is needed here.
        if (kt > 0) {
            uint32_t od[32];
            TCGEN05_LD_X32(od, tmem + TC_O + ch * 32);
            TCGEN05_WAIT_LD();
            #pragma unroll
            for (int j = 0; j < 32; j++)
                od[j] = __float_as_uint(__uint_as_float(od[j]) * alpha);
            TCGEN05_ST_X32(tmem + TC_O + ch * 32, od);
        }
        TCGEN05_WAIT_ST();
        TCGEN05_FENCE_BEFORE();
        __syncthreads();   // P + O TMEM stores done CTA-wide; redB visible

        const float osum = redB[(1 - ch) * 128 + r];
        l_run = l_run * alpha + sum + osum;
        m_run = mn;

        // MMA2: O += P @ V^T (3-term split-bf16)
        if (tid == 0) {
            TCGEN05_FENCE_AFTER();
            const uint64_t dvh = MAKE_DESC(stg + 32768);
            const uint64_t dvl = MAKE_DESC(stg + 49152);
            const int voff[8] = {0, 2, 4, 6, 512, 514, 516, 518};
            #pragma unroll
            for (int ks = 0; ks < 8; ks++)
                mma_ts(tmem + TC_O, tmem + TC_PH + ks * 8, dvh + voff[ks], IDESC_N64,
                       !(kt == 0 && ks == 0));
            #pragma unroll
            for (int ks = 0; ks < 8; ks++)
                mma_ts(tmem + TC_O, tmem + TC_PH + ks * 8, dvl + voff[ks], IDESC_N64, true);
            #pragma unroll
            for (int ks = 0; ks < 8; ks++)
                mma_ts(tmem + TC_O, tmem + TC_PL + ks * 8, dvh + voff[ks], IDESC_N64, true);
            TCGEN05_COMMIT(sb + F_OD(s));
        }

        // All threads: wait MMA2 before next iteration (frees stage s, O stable).
        MBARRIER_WAIT_PARITY(sb + F_OD(s), p2);
        TCGEN05_FENCE_AFTER();
    }

    // Epilogue: O is final (last OD wait happened inside the loop).
    uint32_t od[32];
    TCGEN05_LD_X32(od, tmem + TC_O + ch * 32);
    TCGEN05_WAIT_LD();
    TCGEN05_FENCE_BEFORE();

    const float inv = 1.f / l_run;
    const int srow = qt * 128 + r;
    float* dstp = g_ctx + ((size_t)blockIdx.z * SEQ + srow) * DMODEL + blockIdx.y * DK + ch * 32;
    #pragma unroll
    for (int c = 0; c < 32; c += 4) {
        float4 v = make_float4(__uint_as_float(od[c]) * inv, __uint_as_float(od[c + 1]) * inv,
                               __uint_as_float(od[c + 2]) * inv, __uint_as_float(od[c + 3]) * inv);
        *reinterpret_cast<float4*>(dstp + c) = v;
    }

    __syncthreads();
    if ((tid >> 5) == 0) {
        TCGEN05_RELINQ();
        TCGEN05_DEALLOC(tmem, 512);
    }
#endif
}

// ---------------- FFMA SGEMM fallback (plain sm_103 path) -------------------
__global__ void __launch_bounds__(256)
sgemm_nt(const float* __restrict__ A, const float* __restrict__ W,
         float* __restrict__ Cflat, int dst) {
#if !HAS_TC
    __shared__ float sA[8][128];
    __shared__ float sB[8][128];

    const int tid = threadIdx.x;
    const int lr = tid >> 1;
    const int lc = (tid & 1) << 2;
    const int m0 = blockIdx.y * 128;
    const int n0 = blockIdx.x * 128;
    const int tn = (tid & 15) << 3;
    const int tm = (tid >> 4) << 3;

    const float* Aptr = A + (size_t)(m0 + lr) * DMODEL + lc;
    const float* Wptr = W + (size_t)(n0 + lr) * DMODEL + lc;

    float acc[8][8];
    #pragma unroll
    for (int i = 0; i < 8; i++)
        #pragma unroll
        for (int j = 0; j < 8; j++) acc[i][j] = 0.f;

    for (int k0 = 0; k0 < DMODEL; k0 += 8) {
        float4 av = *reinterpret_cast<const float4*>(Aptr + k0);
        float4 wv = *reinterpret_cast<const float4*>(Wptr + k0);
        __syncthreads();
        sA[lc + 0][lr] = av.x; sA[lc + 1][lr] = av.y;
        sA[lc + 2][lr] = av.z; sA[lc + 3][lr] = av.w;
        sB[lc + 0][lr] = wv.x; sB[lc + 1][lr] = wv.y;
        sB[lc + 2][lr] = wv.z; sB[lc + 3][lr] = wv.w;
        __syncthreads();

        #pragma unroll
        for (int kk = 0; kk < 8; kk++) {
            float a[8], b[8];
            *reinterpret_cast<float4*>(a)     = *reinterpret_cast<const float4*>(&sA[kk][tm]);
            *reinterpret_cast<float4*>(a + 4) = *reinterpret_cast<const float4*>(&sA[kk][tm + 4]);
            *reinterpret_cast<float4*>(b)     = *reinterpret_cast<const float4*>(&sB[kk][tn]);
            *reinterpret_cast<float4*>(b + 4) = *reinterpret_cast<const float4*>(&sB[kk][tn + 4]);
            #pragma unroll
            for (int i = 0; i < 8; i++)
                #pragma unroll
                for (int j = 0; j < 8; j++)
                    acc[i][j] += a[i] * b[j];
        }
    }

    if (dst < 3) {
        float* O = (dst == 0) ? g_qh : (dst == 1) ? g_kh : g_vh;
        #pragma unroll
        for (int i = 0; i < 8; i++) {
            const int m = m0 + tm + i;
            const int b = m >> 11;
            const int s = m & (SEQ - 1);
            #pragma unroll
            for (int j = 0; j < 8; j++) {
                const int n = n0 + tn + j;
                const int h  = n >> 6;
                const int dk = n & 63;
                O[(((size_t)(b * NHEAD + h) * SEQ) + s) * DK + dk] = acc[i][j];
            }
        }
    } else {
        #pragma unroll
        for (int i = 0; i < 8; i++) {
            const int m = m0 + tm + i;
            float* row = Cflat + (size_t)m * DMODEL + n0 + tn;
            #pragma unroll
            for (int j = 0; j < 8; j += 4) {
                float4 v = make_float4(acc[i][j], acc[i][j + 1], acc[i][j + 2], acc[i][j + 3]);
                *reinterpret_cast<float4*>(row + j) = v;
            }
        }
    }
#endif
}

// ---------------- FFMA flash attention fallback ------------------------------
__device__ __forceinline__ float redmax16(float v) {
    #pragma unroll
    for (int o = 8; o; o >>= 1) v = fmaxf(v, __shfl_xor_sync(0xffffffffu, v, o));
    return v;
}
__device__ __forceinline__ float redsum16(float v) {
    #pragma unroll
    for (int o = 8; o; o >>= 1) v += __shfl_xor_sync(0xffffffffu, v, o);
    return v;
}

__global__ void __launch_bounds__(256)
flash_attn(const int* __restrict__ mask) {
#if !HAS_TC
    __shared__ float sQ[64][64];
    __shared__ float sKt[64][68];
    __shared__ float sV[64][68];
    __shared__ float sP[64][68];
    __shared__ int   sMask[64];

    const int tid = threadIdx.x;
    const int tx = tid & 15;
    const int ty = tid >> 4;
    const int bh = blockIdx.z * NHEAD + blockIdx.y;

    const float* Q = g_qh + ((size_t)bh * SEQ + blockIdx.x * 64) * DK;
    const float* K = g_kh + (size_t)bh * SEQ * DK;
    const float* V = g_vh + (size_t)bh * SEQ * DK;
    const int* mk = mask + blockIdx.z * SEQ;

    #pragma unroll
    for (int i = 0; i < 4; i++) {
        int lin = i * 256 + tid;
        int r = lin >> 4, c = (lin & 15) << 2;
        *reinterpret_cast<float4*>(&sQ[r][c]) =
            *reinterpret_cast<const float4*>(Q + r * DK + c);
    }

    float m_run[4], l_run[4], o[4][4];
    #pragma unroll
    for (int i = 0; i < 4; i++) {
        m_run[i] = -INFINITY; l_run[i] = 0.f;
        #pragma unroll
        for (int j = 0; j < 4; j++) o[i][j] = 0.f;
    }

    const float scale = 0.125f;

    for (int j0 = 0; j0 < SEQ; j0 += 64) {
        __syncthreads();
        #pragma unroll
        for (int i = 0; i < 4; i++) {
            int lin = i * 256 + tid;
            int r = lin >> 4, c = (lin & 15) << 2;
            float4 kv = *reinterpret_cast<const float4*>(K + (size_t)(j0 + r) * DK + c);
            sKt[c + 0][r] = kv.x; sKt[c + 1][r] = kv.y;
            sKt[c + 2][r] = kv.z; sKt[c + 3][r] = kv.w;
            *reinterpret_cast<float4*>(&sV[r][c]) =
                *reinterpret_cast<const float4*>(V + (size_t)(j0 + r) * DK + c);
        }
        if (tid < 64) sMask[tid] = mk[j0 + tid];
        __syncthreads();

        float s[4][4];
        #pragma unroll
        for (int i = 0; i < 4; i++)
            #pragma unroll
            for (int j = 0; j < 4; j++) s[i][j] = 0.f;

        #pragma unroll
        for (int kk = 0; kk < 64; kk++) {
            float a0 = sQ[ty * 4 + 0][kk];
            float a1 = sQ[ty * 4 + 1][kk];
            float a2 = sQ[ty * 4 + 2][kk];
            float a3 = sQ[ty * 4 + 3][kk];
            float4 bv = *reinterpret_cast<const float4*>(&sKt[kk][tx * 4]);
            s[0][0] += a0 * bv.x; s[0][1] += a0 * bv.y; s[0][2] += a0 * bv.z; s[0][3] += a0 * bv.w;
            s[1][0] += a1 * bv.x; s[1][1] += a1 * bv.y; s[1][2] += a1 * bv.z; s[1][3] += a1 * bv.w;
            s[2][0] += a2 * bv.x; s[2][1] += a2 * bv.y; s[2][2] += a2 * bv.z; s[2][3] += a2 * bv.w;
            s[3][0] += a3 * bv.x; s[3][1] += a3 * bv.y; s[3][2] += a3 * bv.z; s[3][3] += a3 * bv.w;
        }

        int mk0 = sMask[tx * 4 + 0], mk1 = sMask[tx * 4 + 1];
        int mk2 = sMask[tx * 4 + 2], mk3 = sMask[tx * 4 + 3];
        #pragma unroll
        for (int i = 0; i < 4; i++) {
            s[i][0] = (mk0 == 0) ? -1e9f : s[i][0] * scale;
            s[i][1] = (mk1 == 0) ? -1e9f : s[i][1] * scale;
            s[i][2] = (mk2 == 0) ? -1e9f : s[i][2] * scale;
            s[i][3] = (mk3 == 0) ? -1e9f : s[i][3] * scale;
        }

        #pragma unroll
        for (int i = 0; i < 4; i++) {
            float rmax = fmaxf(fmaxf(s[i][0], s[i][1]), fmaxf(s[i][2], s[i][3]));
            rmax = redmax16(rmax);
            float mn = fmaxf(m_run[i], rmax);
            float alpha = __expf(m_run[i] - mn);
            float sum = 0.f;
            #pragma unroll
            for (int j = 0; j < 4; j++) {
                float p = __expf(s[i][j] - mn);
                s[i][j] = p;
                sum += p;
            }
            sum = redsum16(sum);
            l_run[i] = l_run[i] * alpha + sum;
            m_run[i] = mn;
            #pragma unroll
            for (int j = 0; j < 4; j++) o[i][j] *= alpha;
        }

        #pragma unroll
        for (int i = 0; i < 4; i++) {
            float4 pv = make_float4(s[i][0], s[i][1], s[i][2], s[i][3]);
            *reinterpret_cast<float4*>(&sP[ty * 4 + i][tx * 4]) = pv;
        }
        __syncthreads();

        #pragma unroll
        for (int kk = 0; kk < 64; kk++) {
            float p0 = sP[ty * 4 + 0][kk];
            float p1 = sP[ty * 4 + 1][kk];
            float p2 = sP[ty * 4 + 2][kk];
            float p3 = sP[ty * 4 + 3][kk];
            float4 vv = *reinterpret_cast<const float4*>(&sV[kk][tx * 4]);
            o[0][0] += p0 * vv.x; o[0][1] += p0 * vv.y; o[0][2] += p0 * vv.z; o[0][3] += p0 * vv.w;
            o[1][0] += p1 * vv.x; o[1][1] += p1 * vv.y; o[1][2] += p1 * vv.z; o[1][3] += p1 * vv.w;
            o[2][0] += p2 * vv.x; o[2][1] += p2 * vv.y; o[2][2] += p2 * vv.z; o[2][3] += p2 * vv.w;
            o[3][0] += p3 * vv.x; o[3][1] += p3 * vv.y; o[3][2] += p3 * vv.z; o[3][3] += p3 * vv.w;
        }
    }

    #pragma unroll
    for (int i = 0; i < 4; i++) {
        float inv = 1.f / l_run[i];
        int row = blockIdx.x * 64 + ty * 4 + i;
        float4 out = make_float4(o[i][0] * inv, o[i][1] * inv, o[i][2] * inv, o[i][3] * inv);
        size_t idx = ((size_t)blockIdx.z * SEQ + row) * DMODEL + blockIdx.y * DK + tx * 4;
        *reinterpret_cast<float4*>(&g_ctx[idx]) = out;
    }
#endif
}

// ---------------- Launch -----------------------------------------------------
extern "C" void kernel_launch(void* const* d_in, const int* in_sizes, int n_in,
                              void* d_out, int out_size) {
    const float* q    = (const float*)d_in[0];
    const float* k    = (const float*)d_in[1];
    const float* v    = (const float*)d_in[2];
    const int*   mask = (const int*)  d_in[3];
    const float* Wq   = (const float*)d_in[4];
    const float* Wk   = (const float*)d_in[5];
    const float* Wv   = (const float*)d_in[6];
    const float* Wo   = (const float*)d_in[7];
    float* out = (float*)d_out;

    float* ctx_ptr = nullptr;
    __nv_bfloat16 *hi_ptr = nullptr, *lo_ptr = nullptr;
    cudaGetSymbolAddress((void**)&ctx_ptr, g_ctx);
    cudaGetSymbolAddress((void**)&hi_ptr, g_hi);
    cudaGetSymbolAddress((void**)&lo_ptr, g_lo);

    cudaFuncSetAttribute(gemm_bf16s, cudaFuncAttributeMaxDynamicSharedMemorySize, GEMM_SMEM);
    cudaFuncSetAttribute(flash_tc, cudaFuncAttributeMaxDynamicSharedMemorySize, FLASH_SMEM);

    dim3 ggrid(8, 32);                          // (N/128, M/128)
    dim3 fa_grid_tc(SEQ / 128, NHEAD, BATCH);   // (16, 16, 2)
    dim3 fa_grid(SEQ / 64, NHEAD, BATCH);       // fallback

    // --- TC path: input converters (no-ops on plain sm_103) ---
    convert_split<<<MROWS * 2, 256>>>(q,  hi_ptr + OFF_Q,  lo_ptr + OFF_Q,  32);
    convert_split<<<MROWS * 2, 256>>>(k,  hi_ptr + OFF_K,  lo_ptr + OFF_K,  32);
    convert_split<<<MROWS * 2, 256>>>(v,  hi_ptr + OFF_V,  lo_ptr + OFF_V,  32);
    convert_split<<<2048, 256>>>(Wq, hi_ptr + OFF_WQ, lo_ptr + OFF_WQ, 8);
    convert_split<<<2048, 256>>>(Wk, hi_ptr + OFF_WK, lo_ptr + OFF_WK, 8);
    convert_split<<<2048, 256>>>(Wv, hi_ptr + OFF_WV, lo_ptr + OFF_WV, 8);
    convert_split<<<2048, 256>>>(Wo, hi_ptr + OFF_WO, lo_ptr + OFF_WO, 8);

    // --- QKV projections (one family active per selected cubin) ---
    gemm_bf16s<<<ggrid, 256, GEMM_SMEM>>>(hi_ptr + OFF_Q, lo_ptr + OFF_Q,
                                          hi_ptr + OFF_WQ, lo_ptr + OFF_WQ, nullptr, 0, 32);
    gemm_bf16s<<<ggrid, 256, GEMM_SMEM>>>(hi_ptr + OFF_K, lo_ptr + OFF_K,
                                          hi_ptr + OFF_WK, lo_ptr + OFF_WK, nullptr, 1, 32);
    gemm_bf16s<<<ggrid, 256, GEMM_SMEM>>>(hi_ptr + OFF_V, lo_ptr + OFF_V,
                                          hi_ptr + OFF_WV, lo_ptr + OFF_WV, nullptr, 2, 32);
    sgemm_nt<<<ggrid, 256>>>(q, Wq, nullptr, 0);
    sgemm_nt<<<ggrid, 256>>>(k, Wk, nullptr, 1);
    sgemm_nt<<<ggrid, 256>>>(v, Wv, nullptr, 2);

    // --- Attention ---
    flash_tc<<<fa_grid_tc, 256, FLASH_SMEM>>>(mask);
    flash_attn<<<fa_grid, 256>>>(mask);

    // --- Output projection ---
    convert_split<<<MROWS * 2, 256>>>(ctx_ptr, hi_ptr + OFF_CTX, lo_ptr + OFF_CTX, 32);
    gemm_bf16s<<<ggrid, 256, GEMM_SMEM>>>(hi_ptr + OFF_CTX, lo_ptr + OFF_CTX,
                                          hi_ptr + OFF_WO, lo_ptr + OFF_WO, out, 3, 32);
    sgemm_nt<<<ggrid, 256>>>(ctx_ptr, Wo, out, 3);
}